// round 15
// baseline (speedup 1.0000x reference)
#include <cuda_runtime.h>
#include <math.h>
#include <stdint.h>

#define NN   512
#define DD   32

// ---------------- device scratch ----------------
__device__ float    g_h[NN * DD];        // fp32 state (GRU math)
__device__ uint32_t g_hb[NN * 16];       // bf16x2-packed h rows (16 words/row)
__device__ float    g_v[NN * 64];
__device__ float    g_msum[NN * DD];
__device__ float    g_Jt[NN * NN];

// ---------------- helpers ----------------
static __device__ __forceinline__ uint32_t cvt2(float lo, float hi) {
    uint32_t r;
    asm("cvt.rn.bf16x2.f32 %0, %1, %2;" : "=r"(r) : "f"(hi), "f"(lo));
    return r;
}
static __device__ __forceinline__ void mma16816(float* d, const uint32_t* a,
                                                uint32_t b0, uint32_t b1) {
    asm volatile(
        "mma.sync.aligned.m16n8k16.row.col.f32.bf16.bf16.f32 "
        "{%0,%1,%2,%3}, {%4,%5,%6,%7}, {%8,%9}, {%0,%1,%2,%3};"
        : "+f"(d[0]), "+f"(d[1]), "+f"(d[2]), "+f"(d[3])
        : "r"(a[0]), "r"(a[1]), "r"(a[2]), "r"(a[3]), "r"(b0), "r"(b1));
}

// ---------------- init ----------------
__global__ void k_init() {
    int t = blockIdx.x * blockDim.x + threadIdx.x;
    if (t < NN * DD) g_h[t] = 0.f;
    if (t < NN * 16) g_hb[t] = 0u;
}

// ---------------- transpose J ----------------
__global__ void k_tr(const float* __restrict__ J) {
    __shared__ float tile[32][33];
    int bx = blockIdx.x * 32, by = blockIdx.y * 32;
    int tx = threadIdx.x, ty = threadIdx.y;
    for (int yy = ty; yy < 32; yy += 8)
        tile[yy][tx] = J[(by + yy) * NN + bx + tx];
    __syncthreads();
    for (int yy = ty; yy < 32; yy += 8)
        g_Jt[(size_t)(bx + yy) * NN + by + tx] = tile[tx][yy];
}

// ---------------- v precompute (h@Wj^T + b*wbj + b1) ----------------
__global__ void __launch_bounds__(256) k_v(const float* __restrict__ b,
                                           const float* __restrict__ W1,  // (64,67)
                                           const float* __restrict__ b1) {
    __shared__ float W1s[64][35];
    __shared__ float hs[8][32];
    __shared__ float bv[8];
    int t = threadIdx.x;
    int n0 = blockIdx.x * 8;
    for (int idx = t; idx < 64 * 32; idx += 256)
        W1s[idx >> 5][idx & 31] = W1[(idx >> 5) * 67 + 32 + (idx & 31)];
    if (t < 64) W1s[t][32] = W1[t * 67 + 66];
    {
        int nl = t >> 5, c = t & 31;
        hs[nl][c] = g_h[(n0 + nl) * DD + c];
    }
    if (t < 8) bv[t] = b[n0 + t];
    __syncthreads();
    int k = t & 63;
    int nlb = t >> 6;
    float b1k = b1[k];
#pragma unroll
    for (int rep = 0; rep < 2; rep++) {
        int nl = nlb + rep * 4;
        float vv = bv[nl] * W1s[k][32] + b1k;
#pragma unroll
        for (int d = 0; d < DD; d++)
            vv = fmaf(hs[nl][d], W1s[k][d], vv);
        g_v[(n0 + nl) * 64 + k] = vv;
    }
}

// ---------------- edge MLP + message sum: register-resident weights ----------
#define OFF_H   0            // 512*16 words, XOR-swizzled
#define OFF_W0  32768        // [64][28] words
#define OFF_BJ  39936        // 512 words (b,J) bf16x2
#define OFF_WP  41984        // 4*32 f
#define MSG_SMEM 42496

__global__ void __launch_bounds__(128, 2)
k_msg(const float* __restrict__ b_in,
      const float* __restrict__ W1,   // (64,67): [Wi|Wj|wJ|wbi|wbj]
      const float* __restrict__ W2,   // (64,64)
      const float* __restrict__ b2,
      const float* __restrict__ W3,   // (32,64)
      const float* __restrict__ b3,
      const float* __restrict__ v_in) {
    extern __shared__ char sm[];
    uint32_t* h_s  = (uint32_t*)(sm + OFF_H);
    uint32_t (*W0s)[28] = (uint32_t(*)[28])(sm + OFF_W0);
    uint32_t* bj_s = (uint32_t*)(sm + OFF_BJ);
    float (*wpart)[32] = (float(*)[32])(sm + OFF_WP);

    int t = threadIdx.x;
    int lane = t & 31, wid = t >> 5;
    int j = blockIdx.x;

    const int q = lane & 3;
    const int q2 = q * 2;
    const int rsub = lane >> 2;
    const int brow = lane >> 2;
    const int bcol = lane & 3;

    // ---- stage h (swizzled bf16x2 words) via uint4 copies ----
#pragma unroll
    for (int ii = 0; ii < 16; ii++) {
        int idx = t + 128 * ii;
        uint4 g = ((const uint4*)g_hb)[idx];
        int r = idx >> 2, pg = (idx & 3) * 4;
        int pw = pg ^ ((r & 3) << 2);
        *(uint4*)(h_s + r * 16 + pw) = g;
    }
    // ---- stage W0 = [Wi (k0..31) | (wbi,wJ) word16 | zeros] ----
    for (int idx = t; idx < 64 * 28; idx += 128) {
        int r = idx / 28, w = idx % 28;
        uint32_t val = 0;
        if (w < 16) {
            val = cvt2(W1[r * 67 + 2 * w], W1[r * 67 + 2 * w + 1]);
        } else if (w == 16) {
            val = cvt2(W1[r * 67 + 65], W1[r * 67 + 64]);
        }
        W0s[r][w] = val;
    }
    // ---- stage (b, J) pairs ----
    for (int i = t; i < NN; i += 128)
        bj_s[i] = cvt2(b_in[i], g_Jt[(size_t)j * NN + i]);

    // ---- hoist loop-invariant B-fragments + biases into REGISTERS ----
    uint32_t w2f[8][4][2];   // W2 fragments: [nt][kt][pair]
#pragma unroll
    for (int nt = 0; nt < 8; nt++)
#pragma unroll
        for (int kt = 0; kt < 4; kt++) {
            int rr = nt * 8 + brow;
            int c0 = kt * 8 + bcol, c1 = c0 + 4;
            w2f[nt][kt][0] = cvt2(W2[rr * 64 + 2 * c0], W2[rr * 64 + 2 * c0 + 1]);
            w2f[nt][kt][1] = cvt2(W2[rr * 64 + 2 * c1], W2[rr * 64 + 2 * c1 + 1]);
        }
    uint32_t w3f[4][4][2];
#pragma unroll
    for (int nt = 0; nt < 4; nt++)
#pragma unroll
        for (int kt = 0; kt < 4; kt++) {
            int rr = nt * 8 + brow;
            int c0 = kt * 8 + bcol, c1 = c0 + 4;
            w3f[nt][kt][0] = cvt2(W3[rr * 64 + 2 * c0], W3[rr * 64 + 2 * c0 + 1]);
            w3f[nt][kt][1] = cvt2(W3[rr * 64 + 2 * c1], W3[rr * 64 + 2 * c1 + 1]);
        }
    float vvf[8][2], bb2[8][2];
#pragma unroll
    for (int nt = 0; nt < 8; nt++) {
        vvf[nt][0] = v_in[j * 64 + nt * 8 + q2];
        vvf[nt][1] = v_in[j * 64 + nt * 8 + q2 + 1];
        bb2[nt][0] = b2[nt * 8 + q2];
        bb2[nt][1] = b2[nt * 8 + q2 + 1];
    }
    float bb3[4][2];
#pragma unroll
    for (int nt = 0; nt < 4; nt++) {
        bb3[nt][0] = b3[nt * 8 + q2];
        bb3[nt][1] = b3[nt * 8 + q2 + 1];
    }
    __syncthreads();

    float acc[4][2];
#pragma unroll
    for (int nt = 0; nt < 4; nt++) acc[nt][0] = acc[nt][1] = 0.f;

#pragma unroll 1
    for (int tb = wid; tb < 32; tb += 4) {
        int rA = tb * 16 + rsub;
        int rB = rA + 8;
        int xw = (rA & 3) << 2;

        // ---- A0 fragments: [h | b,J | 0] ----
        uint32_t a0[3][4];
#pragma unroll
        for (int kt = 0; kt < 2; kt++) {
            int p = kt * 8 + q;
            a0[kt][0] = h_s[rA * 16 + (p ^ xw)];
            a0[kt][1] = h_s[rB * 16 + (p ^ xw)];
            a0[kt][2] = h_s[rA * 16 + ((p + 4) ^ xw)];
            a0[kt][3] = h_s[rB * 16 + ((p + 4) ^ xw)];
        }
        a0[2][0] = (q == 0) ? bj_s[rA] : 0u;
        a0[2][1] = (q == 0) ? bj_s[rB] : 0u;
        a0[2][2] = 0u;
        a0[2][3] = 0u;

        // ---- MMA0: [h|b|J] @ W0^T (16x64, K=48), W0 from smem ----
        float d0[8][4];
#pragma unroll
        for (int nt = 0; nt < 8; nt++) {
            d0[nt][0] = d0[nt][1] = d0[nt][2] = d0[nt][3] = 0.f;
#pragma unroll
            for (int kt = 0; kt < 3; kt++) {
                uint32_t b0 = W0s[nt * 8 + brow][kt * 8 + bcol];
                uint32_t b1 = W0s[nt * 8 + brow][kt * 8 + bcol + 4];
                mma16816(d0[nt], a0[kt], b0, b1);
            }
        }

        // ---- convert: relu(d0 + v_j) -> MMA1 A-fragments ----
        uint32_t a1[4][4];
#pragma unroll
        for (int kt = 0; kt < 4; kt++) {
            int n0i = 2 * kt, n1i = 2 * kt + 1;
            a1[kt][0] = cvt2(fmaxf(d0[n0i][0] + vvf[n0i][0], 0.f),
                             fmaxf(d0[n0i][1] + vvf[n0i][1], 0.f));
            a1[kt][1] = cvt2(fmaxf(d0[n0i][2] + vvf[n0i][0], 0.f),
                             fmaxf(d0[n0i][3] + vvf[n0i][1], 0.f));
            a1[kt][2] = cvt2(fmaxf(d0[n1i][0] + vvf[n1i][0], 0.f),
                             fmaxf(d0[n1i][1] + vvf[n1i][1], 0.f));
            a1[kt][3] = cvt2(fmaxf(d0[n1i][2] + vvf[n1i][0], 0.f),
                             fmaxf(d0[n1i][3] + vvf[n1i][1], 0.f));
        }

        // ---- MMA1: d1 = m1 @ W2^T (register B-frags) ----
        float d1[8][4];
#pragma unroll
        for (int nt = 0; nt < 8; nt++) {
            d1[nt][0] = d1[nt][1] = d1[nt][2] = d1[nt][3] = 0.f;
#pragma unroll
            for (int kt = 0; kt < 4; kt++)
                mma16816(d1[nt], a1[kt], w2f[nt][kt][0], w2f[nt][kt][1]);
        }

        // ---- convert: relu(d1 + b2) -> MMA2 A-fragments ----
        uint32_t a2f[4][4];
#pragma unroll
        for (int kt = 0; kt < 4; kt++) {
            int n0i = 2 * kt, n1i = 2 * kt + 1;
            a2f[kt][0] = cvt2(fmaxf(d1[n0i][0] + bb2[n0i][0], 0.f),
                              fmaxf(d1[n0i][1] + bb2[n0i][1], 0.f));
            a2f[kt][1] = cvt2(fmaxf(d1[n0i][2] + bb2[n0i][0], 0.f),
                              fmaxf(d1[n0i][3] + bb2[n0i][1], 0.f));
            a2f[kt][2] = cvt2(fmaxf(d1[n1i][0] + bb2[n1i][0], 0.f),
                              fmaxf(d1[n1i][1] + bb2[n1i][1], 0.f));
            a2f[kt][3] = cvt2(fmaxf(d1[n1i][2] + bb2[n1i][0], 0.f),
                              fmaxf(d1[n1i][3] + bb2[n1i][1], 0.f));
        }

        // ---- MMA2: d2 = m2 @ W3^T (register B-frags) + epi ----
#pragma unroll
        for (int nt = 0; nt < 4; nt++) {
            float d2[4] = {0.f, 0.f, 0.f, 0.f};
#pragma unroll
            for (int kt = 0; kt < 4; kt++)
                mma16816(d2, a2f[kt], w3f[nt][kt][0], w3f[nt][kt][1]);
            acc[nt][0] += fmaxf(d2[0] + bb3[nt][0], 0.f) + fmaxf(d2[2] + bb3[nt][0], 0.f);
            acc[nt][1] += fmaxf(d2[1] + bb3[nt][1], 0.f) + fmaxf(d2[3] + bb3[nt][1], 0.f);
        }
    }

    // ---- reduction ----
#pragma unroll
    for (int nt = 0; nt < 4; nt++)
#pragma unroll
        for (int c = 0; c < 2; c++) {
            float v = acc[nt][c];
            v += __shfl_xor_sync(0xFFFFFFFFu, v, 4);
            v += __shfl_xor_sync(0xFFFFFFFFu, v, 8);
            v += __shfl_xor_sync(0xFFFFFFFFu, v, 16);
            acc[nt][c] = v;
        }
    if (lane < 4) {
#pragma unroll
        for (int nt = 0; nt < 4; nt++) {
            wpart[wid][nt * 8 + lane * 2]     = acc[nt][0];
            wpart[wid][nt * 8 + lane * 2 + 1] = acc[nt][1];
        }
    }
    __syncthreads();
    if (t < 32)
        g_msum[j * 32 + t] = wpart[0][t] + wpart[1][t] + wpart[2][t] + wpart[3][t];
}

// ---------------- GRU (also emits bf16x2-packed h) ----------------
__global__ void __launch_bounds__(384) k_gru(const float* __restrict__ Wih,  // (96,64)
                                             const float* __restrict__ Whh,  // (96,32)
                                             const float* __restrict__ bih,
                                             const float* __restrict__ bhh) {
    __shared__ float Wih_s[96][65];
    __shared__ float Whh_s[96][33];
    __shared__ float x_s[4][64];
    __shared__ float gi_s[4][96], gh_s[4][96];
    int t = threadIdx.x;
    int n0 = blockIdx.x * 4;
    for (int idx = t; idx < 96 * 64; idx += 384) Wih_s[idx >> 6][idx & 63] = Wih[idx];
    for (int idx = t; idx < 96 * 32; idx += 384) Whh_s[idx >> 5][idx & 31] = Whh[idx];
    if (t < 256) {
        int nl = t >> 6, c = t & 63;
        x_s[nl][c] = (c < 32) ? g_h[(n0 + nl) * DD + c]
                              : g_msum[(n0 + nl) * DD + (c - 32)];
    }
    __syncthreads();
    int nl = t / 96, q = t % 96;
    float gi = bih[q], gh = bhh[q];
#pragma unroll
    for (int c = 0; c < 64; c++) gi = fmaf(x_s[nl][c], Wih_s[q][c], gi);
#pragma unroll
    for (int c = 0; c < 32; c++) gh = fmaf(x_s[nl][c], Whh_s[q][c], gh);
    gi_s[nl][q] = gi; gh_s[nl][q] = gh;
    __syncthreads();
    if (q < 32) {
        float r  = 1.f / (1.f + expf(-(gi_s[nl][q]      + gh_s[nl][q])));
        float z  = 1.f / (1.f + expf(-(gi_s[nl][32 + q] + gh_s[nl][32 + q])));
        float ng = tanhf(gi_s[nl][64 + q] + r * gh_s[nl][64 + q]);
        float hn = (1.f - z) * ng + z * x_s[nl][q];
        g_h[(n0 + nl) * DD + q] = hn;
        float hi = __shfl_down_sync(0xFFFFFFFFu, hn, 1);
        if ((q & 1) == 0)
            g_hb[(n0 + nl) * 16 + (q >> 1)] = cvt2(hn, hi);
    }
}

// ---------------- readout ----------------
__global__ void k_readout(const float* __restrict__ W1, const float* __restrict__ b1,
                          const float* __restrict__ W2, const float* __restrict__ b2,
                          const float* __restrict__ W3, const float* __restrict__ b3,
                          float* __restrict__ out) {
    int jn = blockIdx.x;
    int k = threadIdx.x;
    __shared__ float hs[DD], y1[64], y2[64];
    if (k < DD) hs[k] = g_h[jn * DD + k];
    __syncthreads();
    float a = b1[k];
    const float* w1 = W1 + k * DD;
#pragma unroll
    for (int c = 0; c < DD; c++) a = fmaf(hs[c], w1[c], a);
    y1[k] = fmaxf(a, 0.f);
    __syncthreads();
    float a2 = b2[k];
    const float* w2 = W2 + k * 64;
#pragma unroll
    for (int c = 0; c < 64; c++) a2 = fmaf(y1[c], w2[c], a2);
    y2[k] = fmaxf(a2, 0.f);
    __syncthreads();
    if (k < 2) {
        float a3 = b3[k];
        const float* w3 = W3 + k * 64;
#pragma unroll
        for (int c = 0; c < 64; c++) a3 = fmaf(y2[c], w3[c], a3);
        a3 = fmaxf(a3, 0.f);
        out[jn * 2 + k] = 1.f / (1.f + expf(-a3));
    }
}

extern "C" void kernel_launch(void* const* d_in, const int* in_sizes, int n_in,
                              void* d_out, int out_size) {
    const float* J   = (const float*)d_in[0];
    const float* b   = (const float*)d_in[1];
    const float* W1  = (const float*)d_in[2];
    const float* b1  = (const float*)d_in[3];
    const float* W2  = (const float*)d_in[4];
    const float* b2  = (const float*)d_in[5];
    const float* W3  = (const float*)d_in[6];
    const float* b3  = (const float*)d_in[7];
    const float* Wih = (const float*)d_in[8];
    const float* Whh = (const float*)d_in[9];
    const float* bih = (const float*)d_in[10];
    const float* bhh = (const float*)d_in[11];
    const float* rW1 = (const float*)d_in[12];
    const float* rb1 = (const float*)d_in[13];
    const float* rW2 = (const float*)d_in[14];
    const float* rb2 = (const float*)d_in[15];
    const float* rW3 = (const float*)d_in[16];
    const float* rb3 = (const float*)d_in[17];
    float* out = (float*)d_out;

    static float* g_v_ptr = nullptr;
    if (!g_v_ptr) cudaGetSymbolAddress((void**)&g_v_ptr, g_v);

    cudaFuncSetAttribute(k_msg, cudaFuncAttributeMaxDynamicSharedMemorySize,
                         MSG_SMEM);

    k_init<<<16, 1024>>>();
    k_tr<<<dim3(16, 16), dim3(32, 8)>>>(J);
    for (int s = 0; s < 5; s++) {
        k_v<<<64, 256>>>(b, W1, b1);
        k_msg<<<NN, 128, MSG_SMEM>>>(b, W1, W2, b2, W3, b3, g_v_ptr);
        k_gru<<<128, 384>>>(Wih, Whh, bih, bhh);
    }
    k_readout<<<NN, 64>>>(rW1, rb1, rW2, rb2, rW3, rb3, out);
}

// round 16
// speedup vs baseline: 1.4585x; 1.4585x over previous
#include <cuda_runtime.h>
#include <math.h>
#include <stdint.h>

#define NN   512
#define DD   32

// ---------------- device scratch ----------------
__device__ float    g_h[NN * DD];        // fp32 state
__device__ uint4    g_ub4[NN * 8];       // u packed bf16x2: 32 words/row (as uint4)
__device__ float    g_v[NN * 64];
__device__ float    g_msum[NN * DD];
__device__ float    g_Jt[NN * NN];

// ---------------- helpers ----------------
static __device__ __forceinline__ uint32_t cvt2(float lo, float hi) {
    uint32_t r;
    asm("cvt.rn.bf16x2.f32 %0, %1, %2;" : "=r"(r) : "f"(hi), "f"(lo));
    return r;
}
static __device__ __forceinline__ uint32_t fma2b(uint32_t a, uint32_t b, uint32_t c) {
    uint32_t d;
    asm("fma.rn.bf16x2 %0, %1, %2, %3;" : "=r"(d) : "r"(a), "r"(b), "r"(c));
    return d;
}
static __device__ __forceinline__ uint32_t addrelu2b(uint32_t a, uint32_t b) {
    uint32_t d;
    asm("{ .reg .b32 t;\n add.rn.bf16x2 t, %1, %2;\n max.bf16x2 %0, t, %3; }"
        : "=r"(d) : "r"(a), "r"(b), "r"(0u));
    return d;
}
static __device__ __forceinline__ void mma16816(float* d, const uint32_t* a,
                                                uint32_t b0, uint32_t b1) {
    asm volatile(
        "mma.sync.aligned.m16n8k16.row.col.f32.bf16.bf16.f32 "
        "{%0,%1,%2,%3}, {%4,%5,%6,%7}, {%8,%9}, {%0,%1,%2,%3};"
        : "+f"(d[0]), "+f"(d[1]), "+f"(d[2]), "+f"(d[3])
        : "r"(a[0]), "r"(a[1]), "r"(a[2]), "r"(a[3]), "r"(b0), "r"(b1));
}

// ---------------- init ----------------
__global__ void k_init() {
    int t = blockIdx.x * blockDim.x + threadIdx.x;
    if (t < NN * DD) g_h[t] = 0.f;
}

// ---------------- transpose J ----------------
__global__ void k_tr(const float* __restrict__ J) {
    __shared__ float tile[32][33];
    int bx = blockIdx.x * 32, by = blockIdx.y * 32;
    int tx = threadIdx.x, ty = threadIdx.y;
    for (int yy = ty; yy < 32; yy += 8)
        tile[yy][tx] = J[(by + yy) * NN + bx + tx];
    __syncthreads();
    for (int yy = ty; yy < 32; yy += 8)
        g_Jt[(size_t)(bx + yy) * NN + by + tx] = tile[tx][yy];
}

// ---------------- u/v precompute (u -> packed bf16, v -> fp32) ----------------
__global__ void __launch_bounds__(256) k_uv(const float* __restrict__ b,
                                            const float* __restrict__ W1,  // (64,67)
                                            const float* __restrict__ b1) {
    __shared__ float W1s[64][69];
    __shared__ float hs[8][32];
    __shared__ float bv[8];
    int t = threadIdx.x;
    int n0 = blockIdx.x * 8;
    for (int idx = t; idx < 64 * 67; idx += 256)
        W1s[idx / 67][idx % 67] = W1[idx];
    {
        int nl = t >> 5, c = t & 31;
        hs[nl][c] = g_h[(n0 + nl) * DD + c];
    }
    if (t < 8) bv[t] = b[n0 + t];
    __syncthreads();
    int k = t & 63;
    int nlb = t >> 6;
    float b1k = b1[k];
    uint32_t* ub = (uint32_t*)g_ub4;
#pragma unroll
    for (int rep = 0; rep < 2; rep++) {
        int nl = nlb + rep * 4;
        float uu = bv[nl] * W1s[k][65];
        float vv = bv[nl] * W1s[k][66] + b1k;
#pragma unroll
        for (int d = 0; d < DD; d++) {
            uu = fmaf(hs[nl][d], W1s[k][d], uu);
            vv = fmaf(hs[nl][d], W1s[k][DD + d], vv);
        }
        g_v[(n0 + nl) * 64 + k] = vv;
        float u_hi = __shfl_down_sync(0xFFFFFFFFu, uu, 1);
        if ((k & 1) == 0)
            ub[(n0 + nl) * 32 + (k >> 1)] = cvt2(uu, u_hi);
    }
}

// ---------------- edge MLP + message sum: 2-MMA chain, bf16-SIMD m1 build ----
// 512 blocks (one per j), 128 threads = 4 warps, 8 m16 i-tiles per warp.
// Per tile: warp-private coalesced u-tile stage (2KB smem, XOR-swizzled,
// conflict-free LDS) -> bf16x2 SIMD m1 = relu(u + J*wJ + v) -> MMA1 (W2) ->
// relu+b2 reg-convert -> MMA2 (W3) -> relu+b3 column accumulate.
__global__ void __launch_bounds__(128, 4)
k_msg(const float* __restrict__ W1,   // (64,67)
      const float* __restrict__ W2,   // (64,64)
      const float* __restrict__ b2,
      const float* __restrict__ W3,   // (32,64)
      const float* __restrict__ b3,
      const float* __restrict__ v_in) {
    __shared__ uint32_t uw_s[4][512];   // per-warp u tile: 16 rows x 32 words, swizzled
    __shared__ uint32_t W2s[64][36];
    __shared__ uint32_t W3s[32][36];
    __shared__ uint32_t Jc_s[NN];       // (J,J) bf16x2
    __shared__ float b2_s[64], b3_s[32];
    __shared__ float wpart[4][32];

    int t = threadIdx.x;
    int lane = t & 31, wid = t >> 5;
    int j = blockIdx.x;

    const int q = lane & 3;
    const int q2 = q * 2;
    const int rsub = lane >> 2;
    const int brow = lane >> 2;
    const int bcol = lane & 3;

    // ---- stage weights / J column / biases ----
    for (int idx = t; idx < 2048; idx += 128) {
        int r = idx >> 5, w = idx & 31;
        float2 p = *(const float2*)(W2 + r * 64 + 2 * w);
        W2s[r][w] = cvt2(p.x, p.y);
    }
    for (int idx = t; idx < 1024; idx += 128) {
        int r = idx >> 5, w = idx & 31;
        float2 p = *(const float2*)(W3 + r * 64 + 2 * w);
        W3s[r][w] = cvt2(p.x, p.y);
    }
    for (int i = t; i < NN; i += 128) {
        float Jv = g_Jt[(size_t)j * NN + i];
        Jc_s[i] = cvt2(Jv, Jv);
    }
    if (t < 64) b2_s[t] = b2[t];
    if (t < 32) b3_s[t] = b3[t];

    // ---- hoist v_j and wJ as bf16x2 (word-cols q+4t, t=0..7) ----
    uint32_t vJ[8], wJr[8];
#pragma unroll
    for (int tt = 0; tt < 8; tt++) {
        int c0 = tt * 8 + q2;
        vJ[tt]  = cvt2(v_in[j * 64 + c0], v_in[j * 64 + c0 + 1]);
        wJr[tt] = cvt2(W1[c0 * 67 + 64], W1[(c0 + 1) * 67 + 64]);
    }
    __syncthreads();

    uint32_t* uw = uw_s[wid];
    float acc[4][2];
#pragma unroll
    for (int nt = 0; nt < 4; nt++) acc[nt][0] = acc[nt][1] = 0.f;

#pragma unroll 1
    for (int tb = wid; tb < 32; tb += 4) {
        // ---- stage u tile (16 rows x 32 words), coalesced, XOR swizzle ----
        __syncwarp();
#pragma unroll
        for (int ii = 0; ii < 4; ii++) {
            int idx = lane + 32 * ii;          // uint4 index, 128 total
            int row = idx >> 3, p4 = idx & 7;
            uint4 g = g_ub4[tb * 128 + idx];
            *(uint4*)&uw[row * 32 + (p4 ^ (row & 7)) * 4] = g;
        }
        __syncwarp();

        int rAl = rsub, rBl = rsub + 8;        // local rows (both &7 == rsub)
        uint32_t J2a = Jc_s[tb * 16 + rAl];
        uint32_t J2b = Jc_s[tb * 16 + rBl];

        // ---- build m1 A-fragments: relu(u + J*wJ + v), bf16x2 SIMD ----
        uint32_t a1[4][4];
#pragma unroll
        for (int kt = 0; kt < 4; kt++) {
            int t0 = 2 * kt, t1 = 2 * kt + 1;
            int w0 = (t0 ^ rsub) * 4 + q;
            int w1 = (t1 ^ rsub) * 4 + q;
            uint32_t pa0 = fma2b(J2a, wJr[t0], vJ[t0]);
            uint32_t pb0 = fma2b(J2b, wJr[t0], vJ[t0]);
            uint32_t pa1 = fma2b(J2a, wJr[t1], vJ[t1]);
            uint32_t pb1 = fma2b(J2b, wJr[t1], vJ[t1]);
            a1[kt][0] = addrelu2b(uw[rAl * 32 + w0], pa0);
            a1[kt][1] = addrelu2b(uw[rBl * 32 + w0], pb0);
            a1[kt][2] = addrelu2b(uw[rAl * 32 + w1], pa1);
            a1[kt][3] = addrelu2b(uw[rBl * 32 + w1], pb1);
        }

        // ---- MMA1 per kt-pair, immediately convert to MMA2 A-frags ----
        uint32_t a2f[4][4];
#pragma unroll
        for (int ko = 0; ko < 4; ko++) {
            int n0i = 2 * ko, n1i = 2 * ko + 1;
            float d0[4] = {0.f, 0.f, 0.f, 0.f};
            float d1[4] = {0.f, 0.f, 0.f, 0.f};
#pragma unroll
            for (int kt = 0; kt < 4; kt++) {
                mma16816(d0, a1[kt], W2s[n0i * 8 + brow][kt * 8 + bcol],
                                     W2s[n0i * 8 + brow][kt * 8 + bcol + 4]);
                mma16816(d1, a1[kt], W2s[n1i * 8 + brow][kt * 8 + bcol],
                                     W2s[n1i * 8 + brow][kt * 8 + bcol + 4]);
            }
            float p00 = b2_s[n0i * 8 + q2], p01 = b2_s[n0i * 8 + q2 + 1];
            float p10 = b2_s[n1i * 8 + q2], p11 = b2_s[n1i * 8 + q2 + 1];
            a2f[ko][0] = cvt2(fmaxf(d0[0] + p00, 0.f), fmaxf(d0[1] + p01, 0.f));
            a2f[ko][1] = cvt2(fmaxf(d0[2] + p00, 0.f), fmaxf(d0[3] + p01, 0.f));
            a2f[ko][2] = cvt2(fmaxf(d1[0] + p10, 0.f), fmaxf(d1[1] + p11, 0.f));
            a2f[ko][3] = cvt2(fmaxf(d1[2] + p10, 0.f), fmaxf(d1[3] + p11, 0.f));
        }

        // ---- MMA2 + epilogue ----
#pragma unroll
        for (int nt = 0; nt < 4; nt++) {
            float d2[4] = {0.f, 0.f, 0.f, 0.f};
#pragma unroll
            for (int kt = 0; kt < 4; kt++)
                mma16816(d2, a2f[kt], W3s[nt * 8 + brow][kt * 8 + bcol],
                                      W3s[nt * 8 + brow][kt * 8 + bcol + 4]);
            float bb0 = b3_s[nt * 8 + q2];
            float bb1 = b3_s[nt * 8 + q2 + 1];
            acc[nt][0] += fmaxf(d2[0] + bb0, 0.f) + fmaxf(d2[2] + bb0, 0.f);
            acc[nt][1] += fmaxf(d2[1] + bb1, 0.f) + fmaxf(d2[3] + bb1, 0.f);
        }
    }

    // ---- reduction ----
#pragma unroll
    for (int nt = 0; nt < 4; nt++)
#pragma unroll
        for (int c = 0; c < 2; c++) {
            float v = acc[nt][c];
            v += __shfl_xor_sync(0xFFFFFFFFu, v, 4);
            v += __shfl_xor_sync(0xFFFFFFFFu, v, 8);
            v += __shfl_xor_sync(0xFFFFFFFFu, v, 16);
            acc[nt][c] = v;
        }
    if (lane < 4) {
#pragma unroll
        for (int nt = 0; nt < 4; nt++) {
            wpart[wid][nt * 8 + lane * 2]     = acc[nt][0];
            wpart[wid][nt * 8 + lane * 2 + 1] = acc[nt][1];
        }
    }
    __syncthreads();
    if (t < 32)
        g_msum[j * 32 + t] = wpart[0][t] + wpart[1][t] + wpart[2][t] + wpart[3][t];
}

// ---------------- GRU ----------------
__global__ void __launch_bounds__(384) k_gru(const float* __restrict__ Wih,  // (96,64)
                                             const float* __restrict__ Whh,  // (96,32)
                                             const float* __restrict__ bih,
                                             const float* __restrict__ bhh) {
    __shared__ float Wih_s[96][65];
    __shared__ float Whh_s[96][33];
    __shared__ float x_s[4][64];
    __shared__ float gi_s[4][96], gh_s[4][96];
    int t = threadIdx.x;
    int n0 = blockIdx.x * 4;
    for (int idx = t; idx < 96 * 64; idx += 384) Wih_s[idx >> 6][idx & 63] = Wih[idx];
    for (int idx = t; idx < 96 * 32; idx += 384) Whh_s[idx >> 5][idx & 31] = Whh[idx];
    if (t < 256) {
        int nl = t >> 6, c = t & 63;
        x_s[nl][c] = (c < 32) ? g_h[(n0 + nl) * DD + c]
                              : g_msum[(n0 + nl) * DD + (c - 32)];
    }
    __syncthreads();
    int nl = t / 96, q = t % 96;
    float gi = bih[q], gh = bhh[q];
#pragma unroll
    for (int c = 0; c < 64; c++) gi = fmaf(x_s[nl][c], Wih_s[q][c], gi);
#pragma unroll
    for (int c = 0; c < 32; c++) gh = fmaf(x_s[nl][c], Whh_s[q][c], gh);
    gi_s[nl][q] = gi; gh_s[nl][q] = gh;
    __syncthreads();
    if (q < 32) {
        float r  = 1.f / (1.f + expf(-(gi_s[nl][q]      + gh_s[nl][q])));
        float z  = 1.f / (1.f + expf(-(gi_s[nl][32 + q] + gh_s[nl][32 + q])));
        float ng = tanhf(gi_s[nl][64 + q] + r * gh_s[nl][64 + q]);
        g_h[(n0 + nl) * DD + q] = (1.f - z) * ng + z * x_s[nl][q];
    }
}

// ---------------- readout ----------------
__global__ void k_readout(const float* __restrict__ W1, const float* __restrict__ b1,
                          const float* __restrict__ W2, const float* __restrict__ b2,
                          const float* __restrict__ W3, const float* __restrict__ b3,
                          float* __restrict__ out) {
    int jn = blockIdx.x;
    int k = threadIdx.x;
    __shared__ float hs[DD], y1[64], y2[64];
    if (k < DD) hs[k] = g_h[jn * DD + k];
    __syncthreads();
    float a = b1[k];
    const float* w1 = W1 + k * DD;
#pragma unroll
    for (int c = 0; c < DD; c++) a = fmaf(hs[c], w1[c], a);
    y1[k] = fmaxf(a, 0.f);
    __syncthreads();
    float a2 = b2[k];
    const float* w2 = W2 + k * 64;
#pragma unroll
    for (int c = 0; c < 64; c++) a2 = fmaf(y1[c], w2[c], a2);
    y2[k] = fmaxf(a2, 0.f);
    __syncthreads();
    if (k < 2) {
        float a3 = b3[k];
        const float* w3 = W3 + k * 64;
#pragma unroll
        for (int c = 0; c < 64; c++) a3 = fmaf(y2[c], w3[c], a3);
        a3 = fmaxf(a3, 0.f);
        out[jn * 2 + k] = 1.f / (1.f + expf(-a3));
    }
}

extern "C" void kernel_launch(void* const* d_in, const int* in_sizes, int n_in,
                              void* d_out, int out_size) {
    const float* J   = (const float*)d_in[0];
    const float* b   = (const float*)d_in[1];
    const float* W1  = (const float*)d_in[2];
    const float* b1  = (const float*)d_in[3];
    const float* W2  = (const float*)d_in[4];
    const float* b2  = (const float*)d_in[5];
    const float* W3  = (const float*)d_in[6];
    const float* b3  = (const float*)d_in[7];
    const float* Wih = (const float*)d_in[8];
    const float* Whh = (const float*)d_in[9];
    const float* bih = (const float*)d_in[10];
    const float* bhh = (const float*)d_in[11];
    const float* rW1 = (const float*)d_in[12];
    const float* rb1 = (const float*)d_in[13];
    const float* rW2 = (const float*)d_in[14];
    const float* rb2 = (const float*)d_in[15];
    const float* rW3 = (const float*)d_in[16];
    const float* rb3 = (const float*)d_in[17];
    float* out = (float*)d_out;

    static float* g_v_ptr = nullptr;
    if (!g_v_ptr) cudaGetSymbolAddress((void**)&g_v_ptr, g_v);

    k_init<<<16, 1024>>>();
    k_tr<<<dim3(16, 16), dim3(32, 8)>>>(J);
    for (int s = 0; s < 5; s++) {
        k_uv<<<64, 256>>>(b, W1, b1);
        k_msg<<<NN, 128>>>(W1, W2, b2, W3, b3, g_v_ptr);
        k_gru<<<128, 384>>>(Wih, Whh, bih, bhh);
    }
    k_readout<<<NN, 64>>>(rW1, rb1, rW2, rb2, rW3, rb3, out);
}